// round 14
// baseline (speedup 1.0000x reference)
#include <cuda_runtime.h>
#include <cuda_fp16.h>
#include <cstdint>

#define THREADS     256
#define B_ROWS      256
#define M_TILE      128
#define D_K         2048
#define N_FEAT      65536
#define N_TILE      64
#define KC          64
#define NSTAGE      (D_K / KC)            // 32
#define A_ST        (M_TILE * KC * 2)     // 16384 fp16 A per stage
#define B_ST        (N_TILE * KC * 2)     // 8192  fp16 B per stage
#define SMEM_DYN    (128 + 3 * A_ST + 2 * B_ST)   // 65664
#define GRID        ((N_FEAT / N_TILE) * 2)       // 2048

// 1MB fp16 copy of `inputs` (pre-converted once per launch, L2-resident)
__device__ __half g_a16[B_ROWS * D_K];

static __device__ __forceinline__ uint32_t smem_u32(const void* p) {
    uint32_t a;
    asm("{ .reg .u64 t; cvta.to.shared.u64 t, %1; cvt.u32.u64 %0, t; }"
        : "=r"(a) : "l"(p));
    return a;
}

#define CP_ASYNC16(dst, src) \
    asm volatile("cp.async.cg.shared.global [%0], [%1], 16;" \
                 :: "r"(dst), "l"(src) : "memory")
#define CP_COMMIT() asm volatile("cp.async.commit_group;" ::: "memory")
#define CP_WAIT1()  asm volatile("cp.async.wait_group 1;"  ::: "memory")

#define LDSM_X4(r, addr) \
    asm volatile("ldmatrix.sync.aligned.m8n8.x4.shared.b16 {%0,%1,%2,%3}, [%4];" \
        : "=r"((r)[0]), "=r"((r)[1]), "=r"((r)[2]), "=r"((r)[3]) : "r"(addr))

#define MMA16816(c, a, b0, b1) \
    asm volatile("mma.sync.aligned.m16n8k16.row.col.f32.f16.f16.f32 " \
        "{%0,%1,%2,%3}, {%4,%5,%6,%7}, {%8,%9}, {%0,%1,%2,%3};" \
        : "+f"((c)[0]), "+f"((c)[1]), "+f"((c)[2]), "+f"((c)[3]) \
        : "r"((a)[0]), "r"((a)[1]), "r"((a)[2]), "r"((a)[3]), "r"(b0), "r"(b1))

#define STS64(addr, v0, v1) \
    asm volatile("st.shared.v2.b32 [%0], {%1,%2};" \
                 :: "r"(addr), "r"(v0), "r"(v1) : "memory")

// ---------------- pre-kernel: inputs fp32 -> fp16 scratch ----------------
__global__ void cvt_a_kernel(const float* __restrict__ inputs) {
    int i = blockIdx.x * blockDim.x + threadIdx.x;
    if (i < (B_ROWS * D_K) / 2) {
        float2 v = reinterpret_cast<const float2*>(inputs)[i];
        reinterpret_cast<__half2*>(g_a16)[i] = __floats2half2_rn(v.x, v.y);
    }
}

// ---------------- main GEMM kernel: M128 x N64 per CTA, 3 CTAs/SM ----------------
__global__ __launch_bounds__(THREADS, 3)
void gemm_hmma_kernel(const float* __restrict__ feats, float* __restrict__ out) {
    extern __shared__ char dsm[];
    const uint32_t raw = smem_u32(dsm);
    const uint32_t SB  = (raw + 127u) & ~127u;
    const uint32_t BB0 = SB + 3 * A_ST;

    const int tid = threadIdx.x;
    const int wid = tid >> 5;
    const int lid = tid & 31;
    const int wm  = wid & 3;    // 4 M-warps x 32 rows
    const int wn  = wid >> 2;   // 2 N-warps x 32 cols
    const int bid = blockIdx.x;
    const int n0  = (bid >> 1) * N_TILE;   // sibling bids share n-tile -> B via L2
    const int m0  = (bid & 1) * M_TILE;

    // ---- A cp.async staging: 128 rows x 128B/stage; 4x16B per thread ----
    const int arow  = tid >> 1;            // 0..127
    const int cbase = (tid & 1) * 4;       // 16B-chunk base (0 or 4)
    const char* aSrc = (const char*)(g_a16 + (size_t)(m0 + arow) * D_K + cbase * 8);
    uint32_t aoff[4];
    #pragma unroll
    for (int i = 0; i < 4; ++i)
        aoff[i] = ((uint32_t)arow << 7) |
                  ((uint32_t)((cbase + i) ^ (arow & 7)) << 4);

    // ---- B LDG staging: 64 rows x 64 fp32/stage; convert at load (bh[8]) ----
    const int brow = tid >> 2;
    const int bj   = tid & 3;
    const float* bSrc = feats + (size_t)(n0 + brow) * D_K + bj * 4;

    // ---- ldmatrix fragment addressing (swizzle-correct per k-step) ----
    const uint32_t a_lane = (uint32_t)(wm * 32 + (lid & 15)) << 7;
    const uint32_t a_sw   = (uint32_t)(lid & 7);
    const uint32_t a_kc   = (uint32_t)(lid >> 4);
    const uint32_t b_row  = (uint32_t)(wn * 32 + ((lid >> 4) << 3) + (lid & 7));
    const uint32_t b_sw   = b_row & 7;
    const uint32_t b_kc   = (uint32_t)((lid >> 3) & 1);

    float acc[2][4][4];
    #pragma unroll
    for (int mf = 0; mf < 2; ++mf)
        #pragma unroll
        for (int nf = 0; nf < 4; ++nf)
            #pragma unroll
            for (int k = 0; k < 4; ++k)
                acc[mf][nf][k] = 0.0f;

    uint32_t bh[8];   // staged B for next stage, already fp16x2-packed

    // ---- prologue: B(0) LDG+cvt; A(0), A(1) cp.async (distance-2) ----
    #pragma unroll
    for (int i = 0; i < 4; ++i) {
        const float4 v = *reinterpret_cast<const float4*>(bSrc + i * 16);
        __half2 h0 = __floats2half2_rn(v.x, v.y);
        __half2 h1 = __floats2half2_rn(v.z, v.w);
        bh[2*i]   = *reinterpret_cast<uint32_t*>(&h0);
        bh[2*i+1] = *reinterpret_cast<uint32_t*>(&h1);
    }
    #pragma unroll
    for (int i = 0; i < 4; ++i)
        CP_ASYNC16(SB + aoff[i], aSrc + i * 16);
    CP_COMMIT();
    #pragma unroll
    for (int i = 0; i < 4; ++i)
        CP_ASYNC16(SB + A_ST + aoff[i], aSrc + 128 + i * 16);
    CP_COMMIT();

    for (int s = 0; s < NSTAGE; ++s) {
        const uint32_t Ab = SB + (uint32_t)(s % 3) * A_ST;
        const uint32_t Bb = BB0 + (uint32_t)(s & 1) * B_ST;

        // STS B(s) from pre-converted bh
        #pragma unroll
        for (int i = 0; i < 4; ++i) {
            uint32_t ob = ((uint32_t)brow << 7) | ((uint32_t)(bj + 4 * i) << 3);
            ob ^= ((ob >> 3) & 0x70);
            STS64(Bb + ob, bh[2*i], bh[2*i+1]);
        }
        CP_WAIT1();          // A(s) landed (A(s+1) may still be in flight)
        __syncthreads();     // single barrier per stage

        // issue A(s+2) + B(s+1) LDG+cvt (covered by compute below)
        if (s + 2 < NSTAGE) {
            const uint32_t An = SB + (uint32_t)((s + 2) % 3) * A_ST;
            const char* as = aSrc + (size_t)(s + 2) * (KC * 2);
            #pragma unroll
            for (int i = 0; i < 4; ++i)
                CP_ASYNC16(An + aoff[i], as + i * 16);
        }
        CP_COMMIT();
        if (s + 1 < NSTAGE) {
            const int kc1 = (s + 1) * KC;   // FLOAT elements
            #pragma unroll
            for (int i = 0; i < 4; ++i) {
                const float4 v = *reinterpret_cast<const float4*>(bSrc + kc1 + i * 16);
                __half2 h0 = __floats2half2_rn(v.x, v.y);
                __half2 h1 = __floats2half2_rn(v.z, v.w);
                bh[2*i]   = *reinterpret_cast<uint32_t*>(&h0);
                bh[2*i+1] = *reinterpret_cast<uint32_t*>(&h1);
            }
        }

        // ---- compute stage s: 4 k-steps, B frags double-buffered ----
        uint32_t bq0[8], bq1[8];
        {
            const uint32_t ch0 = (b_kc ^ b_sw) << 4;
            LDSM_X4(bq0,     Bb + (b_row << 7) + ch0);
            LDSM_X4(bq0 + 4, Bb + ((b_row + 16u) << 7) + ch0);
        }
        #pragma unroll
        for (int ks = 0; ks < 4; ++ks) {
            uint32_t* bc = (ks & 1) ? bq1 : bq0;
            uint32_t* bn = (ks & 1) ? bq0 : bq1;
            if (ks < 3) {
                const uint32_t chn = ((b_kc + 2u * (ks + 1)) ^ b_sw) << 4;
                LDSM_X4(bn,     Bb + (b_row << 7) + chn);
                LDSM_X4(bn + 4, Bb + ((b_row + 16u) << 7) + chn);
            }

            const uint32_t a_ch = ((a_kc + 2u * ks) ^ a_sw) << 4;
            uint32_t aA[4], aB[4];
            LDSM_X4(aA, Ab + a_lane + a_ch);            // mf=0 (rows +0)
            LDSM_X4(aB, Ab + a_lane + 2048u + a_ch);    // mf=1 (rows +16)
            MMA16816(acc[0][0], aA, bc[0], bc[1]);
            MMA16816(acc[0][1], aA, bc[2], bc[3]);
            MMA16816(acc[0][2], aA, bc[4], bc[5]);
            MMA16816(acc[0][3], aA, bc[6], bc[7]);
            MMA16816(acc[1][0], aB, bc[0], bc[1]);
            MMA16816(acc[1][1], aB, bc[2], bc[3]);
            MMA16816(acc[1][2], aB, bc[4], bc[5]);
            MMA16816(acc[1][3], aB, bc[6], bc[7]);
        }
        // no trailing barrier: next stage's single sync orders reuse hazards
    }

    // ---- epilogue: direct STG.64, 32B-sector aligned ----
    const int mrow = m0 + wm * 32 + (lid >> 2);
    const int ncol = n0 + wn * 32 + 2 * (lid & 3);
    #pragma unroll
    for (int mf = 0; mf < 2; ++mf) {
        float* r0 = out + (size_t)(mrow + mf * 16) * N_FEAT;
        float* r1 = r0 + (size_t)8 * N_FEAT;
        #pragma unroll
        for (int nf = 0; nf < 4; ++nf) {
            const int c = ncol + nf * 8;
            *reinterpret_cast<float2*>(r0 + c) =
                make_float2(acc[mf][nf][0], acc[mf][nf][1]);
            *reinterpret_cast<float2*>(r1 + c) =
                make_float2(acc[mf][nf][2], acc[mf][nf][3]);
        }
    }
}

// ---------------- launch ----------------
extern "C" void kernel_launch(void* const* d_in, const int* in_sizes, int n_in,
                              void* d_out, int out_size) {
    const float* inputs = (const float*)d_in[0];   // [256, 2048] fp32
    const float* feats  = (const float*)d_in[3];   // [65536, 2048] fp32
    float* out = (float*)d_out;                    // [256, 65536] fp32

    cudaFuncSetAttribute(gemm_hmma_kernel,
                         cudaFuncAttributeMaxDynamicSharedMemorySize, SMEM_DYN);

    cvt_a_kernel<<<(B_ROWS * D_K / 2 + 255) / 256, 256>>>(inputs);
    gemm_hmma_kernel<<<GRID, THREADS, SMEM_DYN>>>(feats, out);
}

// round 15
// speedup vs baseline: 1.3826x; 1.3826x over previous
#include <cuda_runtime.h>
#include <cuda_fp16.h>
#include <cstdint>

#define THREADS     512
#define B_ROWS      256
#define D_K         2048
#define N_FEAT      65536
#define N_TILE      128
#define KC          64
#define NSTAGE      (D_K / KC)            // 32
#define A_ST        (B_ROWS * KC * 2)     // 32768 fp16 A per stage
#define B_ST        (N_TILE * KC * 2)     // 16384 fp16 B per stage
#define SMEM_DYN    (128 + 3 * A_ST + 2 * B_ST)   // 131200

// 1MB fp16 copy of `inputs` (pre-converted once per launch, L2-resident)
__device__ __half g_a16[B_ROWS * D_K];

static __device__ __forceinline__ uint32_t smem_u32(const void* p) {
    uint32_t a;
    asm("{ .reg .u64 t; cvta.to.shared.u64 t, %1; cvt.u32.u64 %0, t; }"
        : "=r"(a) : "l"(p));
    return a;
}

#define CP_ASYNC16(dst, src) \
    asm volatile("cp.async.cg.shared.global [%0], [%1], 16;" \
                 :: "r"(dst), "l"(src) : "memory")
#define CP_COMMIT() asm volatile("cp.async.commit_group;" ::: "memory")
#define CP_WAIT1()  asm volatile("cp.async.wait_group 1;"  ::: "memory")

#define LDSM_X4(r, addr) \
    asm volatile("ldmatrix.sync.aligned.m8n8.x4.shared.b16 {%0,%1,%2,%3}, [%4];" \
        : "=r"((r)[0]), "=r"((r)[1]), "=r"((r)[2]), "=r"((r)[3]) : "r"(addr))

#define MMA16816(c, a, b0, b1) \
    asm volatile("mma.sync.aligned.m16n8k16.row.col.f32.f16.f16.f32 " \
        "{%0,%1,%2,%3}, {%4,%5,%6,%7}, {%8,%9}, {%0,%1,%2,%3};" \
        : "+f"((c)[0]), "+f"((c)[1]), "+f"((c)[2]), "+f"((c)[3]) \
        : "r"((a)[0]), "r"((a)[1]), "r"((a)[2]), "r"((a)[3]), "r"(b0), "r"(b1))

#define STS64(addr, v0, v1) \
    asm volatile("st.shared.v2.b32 [%0], {%1,%2};" \
                 :: "r"(addr), "r"(v0), "r"(v1) : "memory")

// ---------------- pre-kernel: inputs fp32 -> fp16 scratch ----------------
__global__ void cvt_a_kernel(const float* __restrict__ inputs) {
    int i = blockIdx.x * blockDim.x + threadIdx.x;
    if (i < (B_ROWS * D_K) / 2) {
        float2 v = reinterpret_cast<const float2*>(inputs)[i];
        reinterpret_cast<__half2*>(g_a16)[i] = __floats2half2_rn(v.x, v.y);
    }
}

// ---------------- main GEMM kernel: M256 x N128, 16 warps (4wm x 4wn) ----------------
__global__ __launch_bounds__(THREADS, 1)
void gemm_hmma_kernel(const float* __restrict__ feats, float* __restrict__ out) {
    extern __shared__ char dsm[];
    const uint32_t raw = smem_u32(dsm);
    const uint32_t SB  = (raw + 127u) & ~127u;
    const uint32_t BB0 = SB + 3 * A_ST;

    const int tid = threadIdx.x;
    const int wid = tid >> 5;
    const int lid = tid & 31;
    const int wm  = wid & 3;    // 4 M-warps x 64 rows
    const int wn  = wid >> 2;   // 4 N-warps x 32 cols
    const int n0  = blockIdx.x * N_TILE;

    // ---- A cp.async staging: 256 rows x 128B/stage; 4x16B per thread ----
    const int arow  = tid >> 1;            // 0..255
    const int cbase = (tid & 1) * 4;       // 16B-chunk base (0 or 4)
    const char* aSrc = (const char*)(g_a16 + (size_t)arow * D_K + cbase * 8);
    uint32_t aoff[4];
    #pragma unroll
    for (int i = 0; i < 4; ++i)
        aoff[i] = ((uint32_t)arow << 7) |
                  ((uint32_t)((cbase + i) ^ (arow & 7)) << 4);

    // ---- B LDG staging: 128 rows x 64 fp32/stage; 4x float4 per thread ----
    const int brow = tid >> 2;             // 0..127
    const int bj   = tid & 3;
    const float* bSrc = feats + (size_t)(n0 + brow) * D_K + bj * 4;

    // ---- ldmatrix fragment addressing (swizzle-correct per k-step) ----
    const uint32_t a_lane = (uint32_t)(wm * 64 + (lid & 15)) << 7;
    const uint32_t a_sw   = (uint32_t)(lid & 7);
    const uint32_t a_kc   = (uint32_t)(lid >> 4);
    const uint32_t b_row  = (uint32_t)(wn * 32 + ((lid >> 4) << 3) + (lid & 7));
    const uint32_t b_sw   = b_row & 7;
    const uint32_t b_kc   = (uint32_t)((lid >> 3) & 1);

    float acc[4][4][4];
    #pragma unroll
    for (int mf = 0; mf < 4; ++mf)
        #pragma unroll
        for (int nf = 0; nf < 4; ++nf)
            #pragma unroll
            for (int k = 0; k < 4; ++k)
                acc[mf][nf][k] = 0.0f;

    float fst[16];   // staged raw fp32 B for current stage

    // ---- prologue: B(0) LDG; A(0), A(1) cp.async (distance-2 pipeline) ----
    #pragma unroll
    for (int i = 0; i < 4; ++i) {
        const float4 v = *reinterpret_cast<const float4*>(bSrc + i * 16);
        fst[i*4+0] = v.x; fst[i*4+1] = v.y; fst[i*4+2] = v.z; fst[i*4+3] = v.w;
    }
    #pragma unroll
    for (int i = 0; i < 4; ++i)
        CP_ASYNC16(SB + aoff[i], aSrc + i * 16);
    CP_COMMIT();
    #pragma unroll
    for (int i = 0; i < 4; ++i)
        CP_ASYNC16(SB + A_ST + aoff[i], aSrc + KC * 2 + i * 16);
    CP_COMMIT();

    for (int s = 0; s < NSTAGE; ++s) {
        const uint32_t Ab = SB + (uint32_t)(s % 3) * A_ST;
        const uint32_t Bb = BB0 + (uint32_t)(s & 1) * B_ST;

        // STS B(s): convert staged fp32 -> fp16 (swizzle recomputed, ALU-cheap)
        #pragma unroll
        for (int i = 0; i < 4; ++i) {
            __half2 h0 = __floats2half2_rn(fst[i*4+0], fst[i*4+1]);
            __half2 h1 = __floats2half2_rn(fst[i*4+2], fst[i*4+3]);
            uint32_t ob = ((uint32_t)brow << 7) | ((uint32_t)(bj + 4 * i) << 3);
            ob ^= ((ob >> 3) & 0x70);
            STS64(Bb + ob,
                  *reinterpret_cast<uint32_t*>(&h0),
                  *reinterpret_cast<uint32_t*>(&h1));
        }
        CP_WAIT1();          // A(s) landed (A(s+1) may still be in flight)
        __syncthreads();     // single barrier per stage

        // issue A(s+2) + B(s+1) LDG (covered by compute below)
        if (s + 2 < NSTAGE) {
            const uint32_t An = SB + (uint32_t)((s + 2) % 3) * A_ST;
            const char* as = aSrc + (size_t)(s + 2) * (KC * 2);
            #pragma unroll
            for (int i = 0; i < 4; ++i)
                CP_ASYNC16(An + aoff[i], as + i * 16);
        }
        CP_COMMIT();
        if (s + 1 < NSTAGE) {
            const int kc1 = (s + 1) * KC;   // FLOAT elements
            #pragma unroll
            for (int i = 0; i < 4; ++i) {
                const float4 v = *reinterpret_cast<const float4*>(bSrc + kc1 + i * 16);
                fst[i*4+0] = v.x; fst[i*4+1] = v.y; fst[i*4+2] = v.z; fst[i*4+3] = v.w;
            }
        }

        // ---- compute stage s: 4 k-steps, software-pipelined fragments ----
        uint32_t bq0[8], bq1[8];   // [0..3]=warp cols 0-15, [4..7]=cols 16-31
        {
            const uint32_t ch0 = (b_kc ^ b_sw) << 4;     // ks=0
            LDSM_X4(bq0,     Bb + (b_row << 7) + ch0);
            LDSM_X4(bq0 + 4, Bb + ((b_row + 16u) << 7) + ch0);
        }
        #pragma unroll
        for (int ks = 0; ks < 4; ++ks) {
            uint32_t* bc = (ks & 1) ? bq1 : bq0;
            uint32_t* bn = (ks & 1) ? bq0 : bq1;
            if (ks < 3) {   // prefetch B frags for ks+1 before MMAs
                const uint32_t chn = ((b_kc + 2u * (ks + 1)) ^ b_sw) << 4;
                LDSM_X4(bn,     Bb + (b_row << 7) + chn);
                LDSM_X4(bn + 4, Bb + ((b_row + 16u) << 7) + chn);
            }

            const uint32_t a_ch = ((a_kc + 2u * ks) ^ a_sw) << 4;
            uint32_t aA[4], aB[4];
            LDSM_X4(aA, Ab + a_lane + a_ch);                      // mf=0
            LDSM_X4(aB, Ab + a_lane + 2048u + a_ch);              // mf=1 prefetch
            MMA16816(acc[0][0], aA, bc[0], bc[1]);
            MMA16816(acc[0][1], aA, bc[2], bc[3]);
            MMA16816(acc[0][2], aA, bc[4], bc[5]);
            MMA16816(acc[0][3], aA, bc[6], bc[7]);
            LDSM_X4(aA, Ab + a_lane + 4096u + a_ch);              // mf=2 prefetch
            MMA16816(acc[1][0], aB, bc[0], bc[1]);
            MMA16816(acc[1][1], aB, bc[2], bc[3]);
            MMA16816(acc[1][2], aB, bc[4], bc[5]);
            MMA16816(acc[1][3], aB, bc[6], bc[7]);
            LDSM_X4(aB, Ab + a_lane + 6144u + a_ch);              // mf=3 prefetch
            MMA16816(acc[2][0], aA, bc[0], bc[1]);
            MMA16816(acc[2][1], aA, bc[2], bc[3]);
            MMA16816(acc[2][2], aA, bc[4], bc[5]);
            MMA16816(acc[2][3], aA, bc[6], bc[7]);
            MMA16816(acc[3][0], aB, bc[0], bc[1]);
            MMA16816(acc[3][1], aB, bc[2], bc[3]);
            MMA16816(acc[3][2], aB, bc[4], bc[5]);
            MMA16816(acc[3][3], aB, bc[6], bc[7]);
        }
        // no trailing barrier: next stage's single sync orders reuse hazards
    }

    // ---- epilogue: direct STG.64, 32B-sector aligned ----
    const int mrow = wm * 64 + (lid >> 2);
    const int ncol = n0 + wn * 32 + 2 * (lid & 3);
    #pragma unroll
    for (int mf = 0; mf < 4; ++mf) {
        float* r0 = out + (size_t)(mrow + mf * 16) * N_FEAT;
        float* r1 = r0 + (size_t)8 * N_FEAT;
        #pragma unroll
        for (int nf = 0; nf < 4; ++nf) {
            const int c = ncol + nf * 8;
            *reinterpret_cast<float2*>(r0 + c) =
                make_float2(acc[mf][nf][0], acc[mf][nf][1]);
            *reinterpret_cast<float2*>(r1 + c) =
                make_float2(acc[mf][nf][2], acc[mf][nf][3]);
        }
    }
}

// ---------------- launch ----------------
extern "C" void kernel_launch(void* const* d_in, const int* in_sizes, int n_in,
                              void* d_out, int out_size) {
    const float* inputs = (const float*)d_in[0];   // [256, 2048] fp32
    const float* feats  = (const float*)d_in[3];   // [65536, 2048] fp32
    float* out = (float*)d_out;                    // [256, 65536] fp32

    cudaFuncSetAttribute(gemm_hmma_kernel,
                         cudaFuncAttributeMaxDynamicSharedMemorySize, SMEM_DYN);

    cvt_a_kernel<<<(B_ROWS * D_K / 2 + 255) / 256, 256>>>(inputs);
    gemm_hmma_kernel<<<N_FEAT / N_TILE, THREADS, SMEM_DYN>>>(feats, out);
}

// round 16
// speedup vs baseline: 1.4765x; 1.0679x over previous
#include <cuda_runtime.h>
#include <cuda_fp16.h>
#include <cstdint>

#define THREADS     256
#define B_ROWS      256
#define D_K         2048
#define N_FEAT      65536
#define N_TILE      64
#define KC          64
#define NSTAGE      (D_K / KC)            // 32
#define A_ST        (B_ROWS * KC * 2)     // 32768 fp16 A per stage
#define B_ST        (N_TILE * KC * 2)     // 8192  fp16 B per stage
#define SMEM_DYN    (128 + 3 * A_ST + 2 * B_ST)   // 114816

// 1MB fp16 copy of `inputs` (pre-converted once per launch, L2-resident)
__device__ __half g_a16[B_ROWS * D_K];

static __device__ __forceinline__ uint32_t smem_u32(const void* p) {
    uint32_t a;
    asm("{ .reg .u64 t; cvta.to.shared.u64 t, %1; cvt.u32.u64 %0, t; }"
        : "=r"(a) : "l"(p));
    return a;
}

#define CP_ASYNC16(dst, src) \
    asm volatile("cp.async.cg.shared.global [%0], [%1], 16;" \
                 :: "r"(dst), "l"(src) : "memory")
#define CP_COMMIT() asm volatile("cp.async.commit_group;" ::: "memory")
#define CP_WAIT1()  asm volatile("cp.async.wait_group 1;"  ::: "memory")

#define LDSM_X4(r, addr) \
    asm volatile("ldmatrix.sync.aligned.m8n8.x4.shared.b16 {%0,%1,%2,%3}, [%4];" \
        : "=r"((r)[0]), "=r"((r)[1]), "=r"((r)[2]), "=r"((r)[3]) : "r"(addr))

#define MMA16816(c, a, b0, b1) \
    asm volatile("mma.sync.aligned.m16n8k16.row.col.f32.f16.f16.f32 " \
        "{%0,%1,%2,%3}, {%4,%5,%6,%7}, {%8,%9}, {%0,%1,%2,%3};" \
        : "+f"((c)[0]), "+f"((c)[1]), "+f"((c)[2]), "+f"((c)[3]) \
        : "r"((a)[0]), "r"((a)[1]), "r"((a)[2]), "r"((a)[3]), "r"(b0), "r"(b1))

#define STS64(addr, v0, v1) \
    asm volatile("st.shared.v2.b32 [%0], {%1,%2};" \
                 :: "r"(addr), "r"(v0), "r"(v1) : "memory")

// ---------------- pre-kernel: inputs fp32 -> fp16 scratch ----------------
__global__ void cvt_a_kernel(const float* __restrict__ inputs) {
    int i = blockIdx.x * blockDim.x + threadIdx.x;
    if (i < (B_ROWS * D_K) / 2) {
        float2 v = reinterpret_cast<const float2*>(inputs)[i];
        reinterpret_cast<__half2*>(g_a16)[i] = __floats2half2_rn(v.x, v.y);
    }
}

// ---------------- main GEMM kernel ----------------
__global__ __launch_bounds__(THREADS, 2)
void gemm_hmma_kernel(const float* __restrict__ feats, float* __restrict__ out) {
    extern __shared__ char dsm[];
    const uint32_t raw = smem_u32(dsm);
    const uint32_t SB  = (raw + 127u) & ~127u;
    const uint32_t BB0 = SB + 3 * A_ST;

    const int tid = threadIdx.x;
    const int wid = tid >> 5;
    const int lid = tid & 31;
    const int wm  = wid & 3;    // 4 M-warps x 64 rows
    const int wn  = wid >> 2;   // 2 N-warps x 32 cols
    const int n0  = blockIdx.x * N_TILE;

    // ---- A cp.async staging: 256 rows x 128B/stage; 8x16B per thread ----
    const char* aSrc = (const char*)(g_a16 + (size_t)(tid >> 3) * D_K + (tid & 7) * 8);
    const uint32_t aOff = ((uint32_t)(tid >> 3) << 7) |
                          ((uint32_t)((tid & 7) ^ ((tid >> 3) & 7)) << 4);

    // ---- B LDG staging: 64 rows x 64 fp32/stage; 4x float4 per thread ----
    const int brow = tid >> 2;
    const int bj   = tid & 3;
    const float* bSrc = feats + (size_t)(n0 + brow) * D_K + bj * 4;

    // ---- ldmatrix fragment addressing (swizzle-correct per k-step) ----
    const uint32_t a_lane = (uint32_t)(wm * 64 + (lid & 15)) << 7;
    const uint32_t a_sw   = (uint32_t)(lid & 7);
    const uint32_t a_kc   = (uint32_t)(lid >> 4);
    const uint32_t b_row  = (uint32_t)(wn * 32 + ((lid >> 4) << 3) + (lid & 7));
    const uint32_t b_sw   = b_row & 7;
    const uint32_t b_kc   = (uint32_t)((lid >> 3) & 1);

    float acc[4][4][4];
    #pragma unroll
    for (int mf = 0; mf < 4; ++mf)
        #pragma unroll
        for (int nf = 0; nf < 4; ++nf)
            #pragma unroll
            for (int k = 0; k < 4; ++k)
                acc[mf][nf][k] = 0.0f;

    uint32_t bh[8];   // staged B for current stage, already fp16x2-packed

    // ---- prologue: B(0) LDG+cvt; A(0), A(1) cp.async (distance-2 pipeline) ----
    #pragma unroll
    for (int i = 0; i < 4; ++i) {
        const float4 v = *reinterpret_cast<const float4*>(bSrc + i * 16);
        __half2 h0 = __floats2half2_rn(v.x, v.y);
        __half2 h1 = __floats2half2_rn(v.z, v.w);
        bh[2*i]   = *reinterpret_cast<uint32_t*>(&h0);
        bh[2*i+1] = *reinterpret_cast<uint32_t*>(&h1);
    }
    #pragma unroll
    for (int i = 0; i < 8; ++i)
        CP_ASYNC16(SB + aOff + i * 4096, aSrc + (size_t)i * 32 * D_K * 2);
    CP_COMMIT();
    #pragma unroll
    for (int i = 0; i < 8; ++i)
        CP_ASYNC16(SB + A_ST + aOff + i * 4096,
                   aSrc + (size_t)KC * 2 + (size_t)i * 32 * D_K * 2);
    CP_COMMIT();

    for (int s = 0; s < NSTAGE; ++s) {
        const uint32_t Ab = SB + (uint32_t)(s % 3) * A_ST;
        const uint32_t Bb = BB0 + (uint32_t)(s & 1) * B_ST;

        // STS B(s): pure data movement (converted at LDG time)
        #pragma unroll
        for (int i = 0; i < 4; ++i) {
            uint32_t ob = ((uint32_t)brow << 7) | ((uint32_t)(bj + 4 * i) << 3);
            ob ^= ((ob >> 3) & 0x70);
            STS64(Bb + ob, bh[2*i], bh[2*i+1]);
        }
        CP_WAIT1();          // A(s) landed (A(s+1) may still be in flight)
        __syncthreads();     // single barrier per stage

        // issue A(s+2) + B(s+1) LDG+cvt (covered by compute below)
        if (s + 2 < NSTAGE) {
            const uint32_t An = SB + (uint32_t)((s + 2) % 3) * A_ST;
            const char* as = aSrc + (size_t)(s + 2) * (KC * 2);
            #pragma unroll
            for (int i = 0; i < 8; ++i)
                CP_ASYNC16(An + aOff + i * 4096, as + (size_t)i * 32 * D_K * 2);
        }
        CP_COMMIT();
        if (s + 1 < NSTAGE) {
            const int kc1 = (s + 1) * KC;   // FLOAT elements
            #pragma unroll
            for (int i = 0; i < 4; ++i) {
                const float4 v = *reinterpret_cast<const float4*>(bSrc + kc1 + i * 16);
                __half2 h0 = __floats2half2_rn(v.x, v.y);
                __half2 h1 = __floats2half2_rn(v.z, v.w);
                bh[2*i]   = *reinterpret_cast<uint32_t*>(&h0);
                bh[2*i+1] = *reinterpret_cast<uint32_t*>(&h1);
            }
        }

        // ---- compute stage s: 4 k-steps, software-pipelined fragments ----
        uint32_t bq0[8], bq1[8];   // [0..3]=cols 0-15, [4..7]=cols 16-31
        {
            const uint32_t ch0 = (b_kc ^ b_sw) << 4;     // ks=0
            LDSM_X4(bq0,     Bb + (b_row << 7) + ch0);
            LDSM_X4(bq0 + 4, Bb + ((b_row + 16u) << 7) + ch0);
        }
        #pragma unroll
        for (int ks = 0; ks < 4; ++ks) {
            uint32_t* bc = (ks & 1) ? bq1 : bq0;
            uint32_t* bn = (ks & 1) ? bq0 : bq1;
            if (ks < 3) {   // prefetch B frags for ks+1 before MMAs
                const uint32_t chn = ((b_kc + 2u * (ks + 1)) ^ b_sw) << 4;
                LDSM_X4(bn,     Bb + (b_row << 7) + chn);
                LDSM_X4(bn + 4, Bb + ((b_row + 16u) << 7) + chn);
            }

            const uint32_t a_ch = ((a_kc + 2u * ks) ^ a_sw) << 4;
            uint32_t aA[4], aB[4];
            LDSM_X4(aA, Ab + a_lane + a_ch);                      // mf=0
            LDSM_X4(aB, Ab + a_lane + 2048u + a_ch);              // mf=1 prefetch
            MMA16816(acc[0][0], aA, bc[0], bc[1]);
            MMA16816(acc[0][1], aA, bc[2], bc[3]);
            MMA16816(acc[0][2], aA, bc[4], bc[5]);
            MMA16816(acc[0][3], aA, bc[6], bc[7]);
            LDSM_X4(aA, Ab + a_lane + 4096u + a_ch);              // mf=2 prefetch
            MMA16816(acc[1][0], aB, bc[0], bc[1]);
            MMA16816(acc[1][1], aB, bc[2], bc[3]);
            MMA16816(acc[1][2], aB, bc[4], bc[5]);
            MMA16816(acc[1][3], aB, bc[6], bc[7]);
            LDSM_X4(aB, Ab + a_lane + 6144u + a_ch);              // mf=3 prefetch
            MMA16816(acc[2][0], aA, bc[0], bc[1]);
            MMA16816(acc[2][1], aA, bc[2], bc[3]);
            MMA16816(acc[2][2], aA, bc[4], bc[5]);
            MMA16816(acc[2][3], aA, bc[6], bc[7]);
            MMA16816(acc[3][0], aB, bc[0], bc[1]);
            MMA16816(acc[3][1], aB, bc[2], bc[3]);
            MMA16816(acc[3][2], aB, bc[4], bc[5]);
            MMA16816(acc[3][3], aB, bc[6], bc[7]);
        }
        // no trailing barrier: next stage's single sync orders reuse hazards
    }

    // ---- epilogue: direct STG.64, 32B-sector aligned ----
    const int mrow = wm * 64 + (lid >> 2);
    const int ncol = n0 + wn * 32 + 2 * (lid & 3);
    #pragma unroll
    for (int mf = 0; mf < 4; ++mf) {
        float* r0 = out + (size_t)(mrow + mf * 16) * N_FEAT;
        float* r1 = r0 + (size_t)8 * N_FEAT;
        #pragma unroll
        for (int nf = 0; nf < 4; ++nf) {
            const int c = ncol + nf * 8;
            *reinterpret_cast<float2*>(r0 + c) =
                make_float2(acc[mf][nf][0], acc[mf][nf][1]);
            *reinterpret_cast<float2*>(r1 + c) =
                make_float2(acc[mf][nf][2], acc[mf][nf][3]);
        }
    }
}

// ---------------- launch ----------------
extern "C" void kernel_launch(void* const* d_in, const int* in_sizes, int n_in,
                              void* d_out, int out_size) {
    const float* inputs = (const float*)d_in[0];   // [256, 2048] fp32
    const float* feats  = (const float*)d_in[3];   // [65536, 2048] fp32
    float* out = (float*)d_out;                    // [256, 65536] fp32

    cudaFuncSetAttribute(gemm_hmma_kernel,
                         cudaFuncAttributeMaxDynamicSharedMemorySize, SMEM_DYN);

    cvt_a_kernel<<<(B_ROWS * D_K / 2 + 255) / 256, 256>>>(inputs);
    gemm_hmma_kernel<<<N_FEAT / N_TILE, THREADS, SMEM_DYN>>>(feats, out);
}

// round 17
// speedup vs baseline: 1.7632x; 1.1942x over previous
#include <cuda_runtime.h>
#include <cuda_fp16.h>
#include <cstdint>

#define THREADS     256
#define B_ROWS      256
#define D_K         2048
#define N_FEAT      65536
#define N_TILE      64
#define KC          64
#define NSTAGE      (D_K / KC)            // 32
#define A_ST        (B_ROWS * KC * 2)     // 32768 fp16 A per stage
#define B_ST        (N_TILE * KC * 2)     // 8192  fp16 B per stage
#define SMEM_DYN    (128 + 3 * A_ST + 2 * B_ST)   // 114816

// 1MB fp16 copy of `inputs` (pre-converted once per launch, L2-resident)
__device__ __half g_a16[B_ROWS * D_K];

static __device__ __forceinline__ uint32_t smem_u32(const void* p) {
    uint32_t a;
    asm("{ .reg .u64 t; cvta.to.shared.u64 t, %1; cvt.u32.u64 %0, t; }"
        : "=r"(a) : "l"(p));
    return a;
}

#define CP_ASYNC16(dst, src) \
    asm volatile("cp.async.cg.shared.global [%0], [%1], 16;" \
                 :: "r"(dst), "l"(src) : "memory")
#define CP_COMMIT() asm volatile("cp.async.commit_group;" ::: "memory")
#define CP_WAIT1()  asm volatile("cp.async.wait_group 1;"  ::: "memory")

#define LDSM_X4(r, addr) \
    asm volatile("ldmatrix.sync.aligned.m8n8.x4.shared.b16 {%0,%1,%2,%3}, [%4];" \
        : "=r"((r)[0]), "=r"((r)[1]), "=r"((r)[2]), "=r"((r)[3]) : "r"(addr))

#define MMA16816(c, a, b0, b1) \
    asm volatile("mma.sync.aligned.m16n8k16.row.col.f32.f16.f16.f32 " \
        "{%0,%1,%2,%3}, {%4,%5,%6,%7}, {%8,%9}, {%0,%1,%2,%3};" \
        : "+f"((c)[0]), "+f"((c)[1]), "+f"((c)[2]), "+f"((c)[3]) \
        : "r"((a)[0]), "r"((a)[1]), "r"((a)[2]), "r"((a)[3]), "r"(b0), "r"(b1))

#define STS64(addr, v0, v1) \
    asm volatile("st.shared.v2.b32 [%0], {%1,%2};" \
                 :: "r"(addr), "r"(v0), "r"(v1) : "memory")

// ---------------- pre-kernel: inputs fp32 -> fp16 scratch ----------------
__global__ void cvt_a_kernel(const float* __restrict__ inputs) {
    int i = blockIdx.x * blockDim.x + threadIdx.x;
    if (i < (B_ROWS * D_K) / 2) {
        float2 v = reinterpret_cast<const float2*>(inputs)[i];
        reinterpret_cast<__half2*>(g_a16)[i] = __floats2half2_rn(v.x, v.y);
    }
}

// ---------------- main GEMM kernel ----------------
__global__ __launch_bounds__(THREADS, 2)
void gemm_hmma_kernel(const float* __restrict__ feats, float* __restrict__ out) {
    extern __shared__ char dsm[];
    const uint32_t raw = smem_u32(dsm);
    const uint32_t SB  = (raw + 127u) & ~127u;
    const uint32_t BB0 = SB + 3 * A_ST;

    const int tid = threadIdx.x;
    const int wid = tid >> 5;
    const int lid = tid & 31;
    const int wm  = wid & 3;    // 4 M-warps x 64 rows
    const int wn  = wid >> 2;   // 2 N-warps x 32 cols
    const int n0  = blockIdx.x * N_TILE;

    // ---- A cp.async staging: 256 rows x 128B/stage; 8x16B per thread ----
    const char* aSrc = (const char*)(g_a16 + (size_t)(tid >> 3) * D_K + (tid & 7) * 8);
    const uint32_t aOff = ((uint32_t)(tid >> 3) << 7) |
                          ((uint32_t)((tid & 7) ^ ((tid >> 3) & 7)) << 4);

    // ---- B LDG staging: 64 rows x 64 fp32/stage; 4x float4 per thread ----
    const int brow = tid >> 2;
    const int bj   = tid & 3;
    const float* bSrc = feats + (size_t)(n0 + brow) * D_K + bj * 4;

    // ---- ldmatrix fragment addressing (swizzle-correct per k-step) ----
    const uint32_t a_lane = (uint32_t)(wm * 64 + (lid & 15)) << 7;
    const uint32_t a_sw   = (uint32_t)(lid & 7);
    const uint32_t a_kc   = (uint32_t)(lid >> 4);
    const uint32_t b_row  = (uint32_t)(wn * 32 + ((lid >> 4) << 3) + (lid & 7));
    const uint32_t b_sw   = b_row & 7;
    const uint32_t b_kc   = (uint32_t)((lid >> 3) & 1);

    float acc[4][4][4];
    #pragma unroll
    for (int mf = 0; mf < 4; ++mf)
        #pragma unroll
        for (int nf = 0; nf < 4; ++nf)
            #pragma unroll
            for (int k = 0; k < 4; ++k)
                acc[mf][nf][k] = 0.0f;

    float fst[16];   // staged raw fp32 B for current stage (cvt deferred to STS)

    // ---- prologue: B(0) LDG; A(0), A(1) cp.async (distance-2 pipeline) ----
    #pragma unroll
    for (int i = 0; i < 4; ++i) {
        const float4 v = *reinterpret_cast<const float4*>(bSrc + i * 16);
        fst[i*4+0] = v.x; fst[i*4+1] = v.y; fst[i*4+2] = v.z; fst[i*4+3] = v.w;
    }
    #pragma unroll
    for (int i = 0; i < 8; ++i)
        CP_ASYNC16(SB + aOff + i * 4096, aSrc + (size_t)i * 32 * D_K * 2);
    CP_COMMIT();
    #pragma unroll
    for (int i = 0; i < 8; ++i)
        CP_ASYNC16(SB + A_ST + aOff + i * 4096,
                   aSrc + (size_t)KC * 2 + (size_t)i * 32 * D_K * 2);
    CP_COMMIT();

    for (int s = 0; s < NSTAGE; ++s) {
        const uint32_t Ab = SB + (uint32_t)(s % 3) * A_ST;
        const uint32_t Bb = BB0 + (uint32_t)(s & 1) * B_ST;

        // STS B(s): convert staged fp32 -> fp16 (swizzle recomputed, ALU-cheap)
        #pragma unroll
        for (int i = 0; i < 4; ++i) {
            __half2 h0 = __floats2half2_rn(fst[i*4+0], fst[i*4+1]);
            __half2 h1 = __floats2half2_rn(fst[i*4+2], fst[i*4+3]);
            uint32_t ob = ((uint32_t)brow << 7) | ((uint32_t)(bj + 4 * i) << 3);
            ob ^= ((ob >> 3) & 0x70);
            STS64(Bb + ob,
                  *reinterpret_cast<uint32_t*>(&h0),
                  *reinterpret_cast<uint32_t*>(&h1));
        }
        CP_WAIT1();          // A(s) landed (A(s+1) may still be in flight)
        __syncthreads();     // single barrier per stage

        // issue A(s+2) + B(s+1) LDG (covered by compute below)
        if (s + 2 < NSTAGE) {
            const uint32_t An = SB + (uint32_t)((s + 2) % 3) * A_ST;
            const char* as = aSrc + (size_t)(s + 2) * (KC * 2);
            #pragma unroll
            for (int i = 0; i < 8; ++i)
                CP_ASYNC16(An + aOff + i * 4096, as + (size_t)i * 32 * D_K * 2);
        }
        CP_COMMIT();
        if (s + 1 < NSTAGE) {
            const int kc1 = (s + 1) * KC;   // FLOAT elements
            #pragma unroll
            for (int i = 0; i < 4; ++i) {
                const float4 v = *reinterpret_cast<const float4*>(bSrc + kc1 + i * 16);
                fst[i*4+0] = v.x; fst[i*4+1] = v.y; fst[i*4+2] = v.z; fst[i*4+3] = v.w;
            }
        }

        // ---- compute stage s: 4 k-steps, software-pipelined fragments ----
        uint32_t bq0[8], bq1[8];   // [0..3]=cols 0-15, [4..7]=cols 16-31
        {
            const uint32_t ch0 = (b_kc ^ b_sw) << 4;     // ks=0
            LDSM_X4(bq0,     Bb + (b_row << 7) + ch0);
            LDSM_X4(bq0 + 4, Bb + ((b_row + 16u) << 7) + ch0);
        }
        #pragma unroll
        for (int ks = 0; ks < 4; ++ks) {
            uint32_t* bc = (ks & 1) ? bq1 : bq0;
            uint32_t* bn = (ks & 1) ? bq0 : bq1;
            if (ks < 3) {   // prefetch B frags for ks+1 before MMAs
                const uint32_t chn = ((b_kc + 2u * (ks + 1)) ^ b_sw) << 4;
                LDSM_X4(bn,     Bb + (b_row << 7) + chn);
                LDSM_X4(bn + 4, Bb + ((b_row + 16u) << 7) + chn);
            }

            const uint32_t a_ch = ((a_kc + 2u * ks) ^ a_sw) << 4;
            uint32_t aA[4], aB[4];
            LDSM_X4(aA, Ab + a_lane + a_ch);                      // mf=0
            LDSM_X4(aB, Ab + a_lane + 2048u + a_ch);              // mf=1 prefetch
            MMA16816(acc[0][0], aA, bc[0], bc[1]);
            MMA16816(acc[0][1], aA, bc[2], bc[3]);
            MMA16816(acc[0][2], aA, bc[4], bc[5]);
            MMA16816(acc[0][3], aA, bc[6], bc[7]);
            LDSM_X4(aA, Ab + a_lane + 4096u + a_ch);              // mf=2 prefetch
            MMA16816(acc[1][0], aB, bc[0], bc[1]);
            MMA16816(acc[1][1], aB, bc[2], bc[3]);
            MMA16816(acc[1][2], aB, bc[4], bc[5]);
            MMA16816(acc[1][3], aB, bc[6], bc[7]);
            LDSM_X4(aB, Ab + a_lane + 6144u + a_ch);              // mf=3 prefetch
            MMA16816(acc[2][0], aA, bc[0], bc[1]);
            MMA16816(acc[2][1], aA, bc[2], bc[3]);
            MMA16816(acc[2][2], aA, bc[4], bc[5]);
            MMA16816(acc[2][3], aA, bc[6], bc[7]);
            MMA16816(acc[3][0], aB, bc[0], bc[1]);
            MMA16816(acc[3][1], aB, bc[2], bc[3]);
            MMA16816(acc[3][2], aB, bc[4], bc[5]);
            MMA16816(acc[3][3], aB, bc[6], bc[7]);
        }
        // no trailing barrier: next stage's single sync orders reuse hazards
    }

    // ---- epilogue: direct STG.64, 32B-sector aligned ----
    const int mrow = wm * 64 + (lid >> 2);
    const int ncol = n0 + wn * 32 + 2 * (lid & 3);
    #pragma unroll
    for (int mf = 0; mf < 4; ++mf) {
        float* r0 = out + (size_t)(mrow + mf * 16) * N_FEAT;
        float* r1 = r0 + (size_t)8 * N_FEAT;
        #pragma unroll
        for (int nf = 0; nf < 4; ++nf) {
            const int c = ncol + nf * 8;
            *reinterpret_cast<float2*>(r0 + c) =
                make_float2(acc[mf][nf][0], acc[mf][nf][1]);
            *reinterpret_cast<float2*>(r1 + c) =
                make_float2(acc[mf][nf][2], acc[mf][nf][3]);
        }
    }
}

// ---------------- launch ----------------
extern "C" void kernel_launch(void* const* d_in, const int* in_sizes, int n_in,
                              void* d_out, int out_size) {
    const float* inputs = (const float*)d_in[0];   // [256, 2048] fp32
    const float* feats  = (const float*)d_in[3];   // [65536, 2048] fp32
    float* out = (float*)d_out;                    // [256, 65536] fp32

    cudaFuncSetAttribute(gemm_hmma_kernel,
                         cudaFuncAttributeMaxDynamicSharedMemorySize, SMEM_DYN);

    cvt_a_kernel<<<(B_ROWS * D_K / 2 + 255) / 256, 256>>>(inputs);
    gemm_hmma_kernel<<<N_FEAT / N_TILE, THREADS, SMEM_DYN>>>(feats, out);
}